// round 7
// baseline (speedup 1.0000x reference)
#include <cuda_runtime.h>
#include <cuda_bf16.h>
#include <cstdint>
#include <math.h>

#define DM 512
#define DI 2048
#define NH 8
#define DKH 64
#define BSZ 32
#define MAXROWS (32*160)
#define MAXKV   (32*640)

// tcgen05 only exists on arch-specific / family-specific targets.
#if defined(__CUDA_ARCH__) && (__CUDA_ARCH__ >= 1000) && \
    (defined(__CUDA_ARCH_FEAT_SM103_ALL) || defined(__CUDA_ARCH_FEAT_SM100_ALL) || \
     defined(__CUDA_ARCH_SPECIFIC__) || defined(__CUDA_ARCH_FAMILY_SPECIFIC__))
#define HAS_T5 1
#else
#define HAS_T5 0
#endif

// ---- fp32 scratch ----
__device__ float g_Q  [MAXROWS*DM];
__device__ float g_K  [MAXKV*DM];
__device__ float g_V  [MAXKV*DM];
__device__ float g_t0 [MAXROWS*DM];
__device__ float g_x  [MAXROWS*DM];

// ---- bf16 hi/lo scratch ----
__device__ __nv_bfloat16 g_predH[MAXKV*DM],   g_predL[MAXKV*DM];
__device__ __nv_bfloat16 g_entH [MAXROWS*DM], g_entL [MAXROWS*DM];
__device__ __nv_bfloat16 g_ctxH [MAXROWS*DM], g_ctxL [MAXROWS*DM];
__device__ __nv_bfloat16 g_xH   [MAXROWS*DM], g_xL   [MAXROWS*DM];
__device__ __nv_bfloat16 g_hH   [MAXROWS*DI], g_hL   [MAXROWS*DI];
__device__ __nv_bfloat16 g_wqH[DM*DM], g_wqL[DM*DM];
__device__ __nv_bfloat16 g_wkH[DM*DM], g_wkL[DM*DM];
__device__ __nv_bfloat16 g_wvH[DM*DM], g_wvL[DM*DM];
__device__ __nv_bfloat16 g_wfH[DM*DM], g_wfL[DM*DM];
__device__ __nv_bfloat16 g_w1H[DI*DM], g_w1L[DI*DM];
__device__ __nv_bfloat16 g_w2H[DM*DI], g_w2L[DM*DI];

__device__ __forceinline__ unsigned pack_bf2(float a, float b) {
    __nv_bfloat162 t = __floats2bfloat162_rn(a, b);
    return *(unsigned*)&t;
}

// ============================================================
// fp32 -> bf16 hi/lo conversion
// ============================================================
__global__ void cvt_hl(const float* __restrict__ in,
                       __nv_bfloat16* __restrict__ hi,
                       __nv_bfloat16* __restrict__ lo, int n4)
{
    int i = blockIdx.x * blockDim.x + threadIdx.x;
    if (i >= n4) return;
    float4 v = ((const float4*)in)[i];
    float h0 = __bfloat162float(__float2bfloat16(v.x));
    float h1 = __bfloat162float(__float2bfloat16(v.y));
    float h2 = __bfloat162float(__float2bfloat16(v.z));
    float h3 = __bfloat162float(__float2bfloat16(v.w));
    uint2 uh, ul;
    uh.x = pack_bf2(v.x, v.y);
    uh.y = pack_bf2(v.z, v.w);
    ul.x = pack_bf2(v.x - h0, v.y - h1);
    ul.y = pack_bf2(v.z - h2, v.w - h3);
    *(uint2*)(hi + 4 * (size_t)i) = uh;
    *(uint2*)(lo + 4 * (size_t)i) = ul;
}

// ============================================================
// GEMM: C[M,N] = A[M,K] @ W[N,K]^T + bias; A,W as bf16 hi/lo,
// 3 MMA passes (AhWh + AhWl + AlWh). CTA tile 128x256.
// tcgen05 SS-mode path on arch-specific builds; mma.sync fallback else.
// ============================================================
#define TBM 128
#define TBN 256
#define TBK 64
#define OFF_AH 0
#define OFF_AL 16384
#define OFF_WH 32768
#define OFF_WL 65536
#define STAGE_BYTES 98304
#define SM_HDR 1024
#define GEMM_SMEM (SM_HDR + 2*STAGE_BYTES)

// fallback tile geometry (128x128 halves)
#define GBM 128
#define GLD 40

// idesc kind::f16: dtype=F32(1<<4), atype=BF16(1<<7), btype=BF16(1<<10),
// (N>>3)<<17, (M>>4)<<24  -> M=128, N=256
#define IDESC_T5 0x8400490u

__device__ __forceinline__ unsigned smem_u32(const void* p) {
    return (unsigned)__cvta_generic_to_shared(p);
}

#if HAS_T5
__device__ __forceinline__ uint64_t make_desc(unsigned addr) {
    // SW128 layout, Blackwell version=1, SBO=64, LBO=1
    return 0x4000404000010000ULL | ((uint64_t)(addr >> 4) & 0x3FFF);
}
__device__ __forceinline__ bool elect1() {
    unsigned p;
    asm volatile("{\n\t.reg .pred p;\n\telect.sync _|p, 0xFFFFFFFF;\n\t"
                 "selp.b32 %0, 1, 0, p;\n\t}" : "=r"(p));
    return p != 0;
}
__device__ __forceinline__ void mbar_init(unsigned addr, unsigned cnt) {
    asm volatile("mbarrier.init.shared.b64 [%0], %1;" :: "r"(addr), "r"(cnt) : "memory");
}
__device__ __forceinline__ void mbar_inval(unsigned addr) {
    asm volatile("mbarrier.inval.shared.b64 [%0];" :: "r"(addr) : "memory");
}
__device__ __forceinline__ void mbar_wait(unsigned addr, unsigned parity) {
    asm volatile(
        "{\n\t.reg .pred P;\n\t"
        "W_%=: mbarrier.try_wait.parity.acquire.cta.shared::cta.b64 P, [%0], %1, 0x989680;\n\t"
        "@P bra D_%=;\n\t"
        "bra W_%=;\n\t"
        "D_%=:\n\t}"
        :: "r"(addr), "r"(parity) : "memory");
}
__device__ __forceinline__ void mma_f16_ss(unsigned d, uint64_t a, uint64_t b,
                                           unsigned idesc, unsigned en) {
    asm volatile(
        "{\n\t.reg .pred p;\n\tsetp.ne.u32 p, %4, 0;\n\t"
        "tcgen05.mma.cta_group::1.kind::f16 [%0], %1, %2, %3, {%5,%5,%5,%5}, p;\n\t}"
        :: "r"(d), "l"(a), "l"(b), "r"(idesc), "r"(en), "r"(0u) : "memory");
}

#define TC_LD32(r, a) \
    asm volatile("tcgen05.ld.sync.aligned.32x32b.x32.b32 " \
        "{%0,%1,%2,%3,%4,%5,%6,%7,%8,%9,%10,%11,%12,%13,%14,%15," \
        "%16,%17,%18,%19,%20,%21,%22,%23,%24,%25,%26,%27,%28,%29,%30,%31}, [%32];" \
        : "=r"((r)[0]),"=r"((r)[1]),"=r"((r)[2]),"=r"((r)[3]), \
          "=r"((r)[4]),"=r"((r)[5]),"=r"((r)[6]),"=r"((r)[7]), \
          "=r"((r)[8]),"=r"((r)[9]),"=r"((r)[10]),"=r"((r)[11]), \
          "=r"((r)[12]),"=r"((r)[13]),"=r"((r)[14]),"=r"((r)[15]), \
          "=r"((r)[16]),"=r"((r)[17]),"=r"((r)[18]),"=r"((r)[19]), \
          "=r"((r)[20]),"=r"((r)[21]),"=r"((r)[22]),"=r"((r)[23]), \
          "=r"((r)[24]),"=r"((r)[25]),"=r"((r)[26]),"=r"((r)[27]), \
          "=r"((r)[28]),"=r"((r)[29]),"=r"((r)[30]),"=r"((r)[31]) \
        : "r"(a))
#endif  // HAS_T5

// mma.sync fallback helpers (legal on plain sm_103)
__device__ __forceinline__ void ldsm_x4(unsigned* r, const void* p) {
    unsigned a = smem_u32(p);
    asm volatile("ldmatrix.sync.aligned.m8n8.x4.shared.b16 {%0,%1,%2,%3}, [%4];"
        : "=r"(r[0]), "=r"(r[1]), "=r"(r[2]), "=r"(r[3]) : "r"(a));
}
__device__ __forceinline__ void ldsm_x2(unsigned* r, const void* p) {
    unsigned a = smem_u32(p);
    asm volatile("ldmatrix.sync.aligned.m8n8.x2.shared.b16 {%0,%1}, [%2];"
        : "=r"(r[0]), "=r"(r[1]) : "r"(a));
}
__device__ __forceinline__ void mma16816(float* c, const unsigned* a, const unsigned* b) {
    asm volatile("mma.sync.aligned.m16n8k16.row.col.f32.bf16.bf16.f32 "
        "{%0,%1,%2,%3}, {%4,%5,%6,%7}, {%8,%9}, {%0,%1,%2,%3};"
        : "+f"(c[0]), "+f"(c[1]), "+f"(c[2]), "+f"(c[3])
        : "r"(a[0]), "r"(a[1]), "r"(a[2]), "r"(a[3]), "r"(b[0]), "r"(b[1]));
}

__device__ __forceinline__ void store_out(float* Cf, __nv_bfloat16* Ch, __nv_bfloat16* Cl,
                                          size_t o, float v0, float v1, float v2, float v3)
{
    if (Cf) {
        *(float4*)(Cf + o) = make_float4(v0, v1, v2, v3);
    }
    if (Ch) {
        float h0 = __bfloat162float(__float2bfloat16(v0));
        float h1 = __bfloat162float(__float2bfloat16(v1));
        float h2 = __bfloat162float(__float2bfloat16(v2));
        float h3 = __bfloat162float(__float2bfloat16(v3));
        uint2 uh, ul;
        uh.x = pack_bf2(v0, v1); uh.y = pack_bf2(v2, v3);
        ul.x = pack_bf2(v0 - h0, v1 - h1); ul.y = pack_bf2(v2 - h2, v3 - h3);
        *(uint2*)(Ch + o) = uh;
        *(uint2*)(Cl + o) = ul;
    }
}

__global__ __launch_bounds__(256, 1)
void gemm_t5(const __nv_bfloat16* __restrict__ Ah, const __nv_bfloat16* __restrict__ Al,
             const int* __restrict__ rmap,
             const __nv_bfloat16* __restrict__ Wh, const __nv_bfloat16* __restrict__ Wl,
             const float* __restrict__ bias,
             float* __restrict__ Cf,
             __nv_bfloat16* __restrict__ Ch, __nv_bfloat16* __restrict__ Cl,
             int M, int N, int K, int relu)
{
    extern __shared__ char sm[];
    const int tid  = threadIdx.x;
    const int wid  = tid >> 5;
    const int lane = tid & 31;
    const int bm = blockIdx.y * TBM;
    const int bn = blockIdx.x * TBN;
    int* irows = (int*)(sm + 512);

    if (tid < TBM) {
        int ar = bm + tid;
        irows[tid] = (ar < M) ? (rmap ? rmap[ar] : ar) : -1;
    }

#if HAS_T5
    const unsigned smb = smem_u32(sm);
    if (wid == 0) {
        asm volatile("tcgen05.alloc.cta_group::1.sync.aligned.shared::cta.b32 [%0], %1;"
            :: "r"(smb), "r"(256u) : "memory");
        asm volatile("tcgen05.relinquish_alloc_permit.cta_group::1.sync.aligned;");
    }
    if (tid == 0) {
        mbar_init(smb + 8, 1);
        mbar_init(smb + 16, 1);
    }
    __syncthreads();

    unsigned tmem;
    asm volatile("ld.shared.b32 %0, [%1];" : "=r"(tmem) : "r"(smb));

    int ph0 = 0, ph1 = 0;
    const int nChunks = K / TBK;

    for (int c = 0; c < nChunks; ++c) {
        const int s = c & 1;
        const unsigned stage = SM_HDR + s * STAGE_BYTES;
        const int k0 = c * TBK;

        if (c >= 2) {
            mbar_wait(smb + 8 + s * 8, s ? ph1 : ph0);
            if (s) ph1 ^= 1; else ph0 ^= 1;
        }

        // ---- fill Ah/Al (128x64) + Wh/Wl (256x64), SW128 swizzled ----
        #pragma unroll
        for (int i = 0; i < 24; ++i) {
            int idx = tid + i * 256;   // 0..6143
            const __nv_bfloat16* src;
            unsigned dstoff;
            int r, c8, grow;
            if (idx < 2048) {
                int j = idx & 1023;
                r = j >> 3; c8 = j & 7;
                grow = irows[r];
                src = (idx < 1024) ? Ah : Al;
                dstoff = (idx < 1024) ? OFF_AH : OFF_AL;
            } else {
                int j = (idx - 2048) & 2047;
                r = j >> 3; c8 = j & 7;
                int wr = bn + r;
                grow = (wr < N) ? wr : -1;
                src = (idx < 4096) ? Wh : Wl;
                dstoff = (idx < 4096) ? OFF_WH : OFF_WL;
            }
            uint4 v = make_uint4(0u, 0u, 0u, 0u);
            if (grow >= 0) {
                v = *(const uint4*)(src + (size_t)grow * K + k0 + c8 * 8);
            }
            unsigned byte = r * 128 + c8 * 16;
            unsigned sw = byte ^ ((byte >> 3) & 0x70);
            *(uint4*)(sm + stage + dstoff + sw) = v;
        }
        __syncthreads();

        if (wid == 0) {
            asm volatile("fence.proxy.async.shared::cta;" ::: "memory");
            if (elect1()) {
                uint64_t dah = make_desc(smb + stage + OFF_AH);
                uint64_t dal = make_desc(smb + stage + OFF_AL);
                uint64_t dwh = make_desc(smb + stage + OFF_WH);
                uint64_t dwl = make_desc(smb + stage + OFF_WL);
                #pragma unroll
                for (int k = 0; k < 4; ++k) {
                    unsigned en0 = (c > 0 || k > 0) ? 1u : 0u;
                    mma_f16_ss(tmem, dah + k * 2, dwh + k * 2, IDESC_T5, en0);
                    mma_f16_ss(tmem, dah + k * 2, dwl + k * 2, IDESC_T5, 1u);
                    mma_f16_ss(tmem, dal + k * 2, dwh + k * 2, IDESC_T5, 1u);
                }
                asm volatile(
                    "tcgen05.commit.cta_group::1.mbarrier::arrive::one.shared::cluster.b64 [%0];"
                    :: "r"(smb + 8 + s * 8) : "memory");
            }
        }
    }

    {
        const int sL = (nChunks - 1) & 1;
        mbar_wait(smb + 8 + sL * 8, sL ? ph1 : ph0);
    }
    asm volatile("tcgen05.fence::after_thread_sync;" ::: "memory");

    // ---- epilogue: warp%4 = row subpartition, warp/4 = column half ----
    const int m = bm + (wid & 3) * 32 + lane;
    const int colbase = (wid >> 2) * 128;
    #pragma unroll
    for (int g = 0; g < 4; ++g) {
        unsigned r32[32];
        TC_LD32(r32, tmem + colbase + g * 32);
        asm volatile("tcgen05.wait::ld.sync.aligned;" ::: "memory");
        if (m < M) {
            int cbase = bn + colbase + g * 32;
            #pragma unroll
            for (int j = 0; j < 8; ++j) {
                float4 bv = *(const float4*)(bias + cbase + j * 4);
                float v0 = __uint_as_float(r32[j*4+0]) + bv.x;
                float v1 = __uint_as_float(r32[j*4+1]) + bv.y;
                float v2 = __uint_as_float(r32[j*4+2]) + bv.z;
                float v3 = __uint_as_float(r32[j*4+3]) + bv.w;
                if (relu) {
                    v0 = fmaxf(v0, 0.f); v1 = fmaxf(v1, 0.f);
                    v2 = fmaxf(v2, 0.f); v3 = fmaxf(v3, 0.f);
                }
                store_out(Cf, Ch, Cl, (size_t)m * N + cbase + j * 4, v0, v1, v2, v3);
            }
        }
    }
    asm volatile("tcgen05.fence::before_thread_sync;" ::: "memory");
    __syncthreads();
    if (tid == 0) {
        mbar_inval(smb + 8);
        mbar_inval(smb + 16);
    }
    if (wid == 0) {
        asm volatile("tcgen05.dealloc.cta_group::1.sync.aligned.b32 %0, %1;"
            :: "r"(tmem), "r"(256u));
    }

#else   // ---------------- mma.sync fallback (plain sm_103) ----------------
    __syncthreads();
    __nv_bfloat16 (*s)[GBM][GLD] = (__nv_bfloat16 (*)[GBM][GLD])(sm + SM_HDR);
    const int wm = wid >> 2;
    const int wn = wid & 3;

    for (int nh = 0; nh < 2; ++nh) {
        const int bnh = bn + nh * 128;
        float acc[4][4][4];
        #pragma unroll
        for (int mi = 0; mi < 4; ++mi) {
            #pragma unroll
            for (int ni = 0; ni < 4; ++ni) {
                #pragma unroll
                for (int j = 0; j < 4; ++j) acc[mi][ni][j] = 0.f;
            }
        }

        for (int k0 = 0; k0 < K; k0 += 32) {
            #pragma unroll
            for (int i = 0; i < 16; ++i) {
                int idx = tid + i * 256;
                int buf = idx >> 10;
                int j   = idx & 1023;
                int r   = j >> 3;
                int c4  = (j & 7) * 4;
                const __nv_bfloat16* src;
                int grow;
                if (buf < 2) {
                    grow = irows[r];
                    src = (buf == 1) ? Al : Ah;
                } else {
                    int wr = bnh + r;
                    grow = (wr < N) ? wr : -1;
                    src = (buf == 3) ? Wl : Wh;
                }
                uint2 v = make_uint2(0u, 0u);
                if (grow >= 0) {
                    v = *(const uint2*)(src + (size_t)grow * K + k0 + c4);
                }
                *(uint2*)&s[buf][r][c4] = v;
            }
            __syncthreads();

            #pragma unroll
            for (int ks = 0; ks < 2; ++ks) {
                const int kk = ks * 16;
                unsigned ah[4][4], al[4][4], bh[4][2], bl[4][2];
                const int lr = lane & 15;
                const int lk = (lane >> 4) * 8;
                #pragma unroll
                for (int mi = 0; mi < 4; ++mi) {
                    ldsm_x4(ah[mi], &s[0][wm * 64 + mi * 16 + lr][kk + lk]);
                    ldsm_x4(al[mi], &s[1][wm * 64 + mi * 16 + lr][kk + lk]);
                }
                const int l8  = lane & 7;
                const int lk2 = ((lane >> 3) & 1) * 8;
                #pragma unroll
                for (int ni = 0; ni < 4; ++ni) {
                    ldsm_x2(bh[ni], &s[2][wn * 32 + ni * 8 + l8][kk + lk2]);
                    ldsm_x2(bl[ni], &s[3][wn * 32 + ni * 8 + l8][kk + lk2]);
                }
                #pragma unroll
                for (int mi = 0; mi < 4; ++mi) {
                    #pragma unroll
                    for (int ni = 0; ni < 4; ++ni) {
                        mma16816(acc[mi][ni], ah[mi], bh[ni]);
                        mma16816(acc[mi][ni], ah[mi], bl[ni]);
                        mma16816(acc[mi][ni], al[mi], bh[ni]);
                    }
                }
            }
            __syncthreads();
        }

        #pragma unroll
        for (int mi = 0; mi < 4; ++mi) {
            int r0 = bm + wm * 64 + mi * 16 + (lane >> 2);
            #pragma unroll
            for (int ni = 0; ni < 4; ++ni) {
                int c = bnh + wn * 32 + ni * 8 + (lane & 3) * 2;
                float b0 = bias[c];
                float b1 = bias[c + 1];
                float v0 = acc[mi][ni][0] + b0;
                float v1 = acc[mi][ni][1] + b1;
                float v2 = acc[mi][ni][2] + b0;
                float v3 = acc[mi][ni][3] + b1;
                if (relu) {
                    v0 = fmaxf(v0, 0.f); v1 = fmaxf(v1, 0.f);
                    v2 = fmaxf(v2, 0.f); v3 = fmaxf(v3, 0.f);
                }
                if (r0 < M) {
                    size_t o = (size_t)r0 * N + c;
                    if (Cf) *(float2*)(Cf + o) = make_float2(v0, v1);
                    if (Ch) {
                        float h0 = __bfloat162float(__float2bfloat16(v0));
                        float h1 = __bfloat162float(__float2bfloat16(v1));
                        *(unsigned*)(Ch + o) = pack_bf2(v0, v1);
                        *(unsigned*)(Cl + o) = pack_bf2(v0 - h0, v1 - h1);
                    }
                }
                if (r0 + 8 < M) {
                    size_t o = (size_t)(r0 + 8) * N + c;
                    if (Cf) *(float2*)(Cf + o) = make_float2(v2, v3);
                    if (Ch) {
                        float h2 = __bfloat162float(__float2bfloat16(v2));
                        float h3 = __bfloat162float(__float2bfloat16(v3));
                        *(unsigned*)(Ch + o) = pack_bf2(v2, v3);
                        *(unsigned*)(Cl + o) = pack_bf2(v2 - h2, v3 - h3);
                    }
                }
            }
        }
        __syncthreads();
    }
#endif
}

// ============================================================
// LayerNorm with residual; optional bf16 hi/lo secondary output.
// ============================================================
__global__ void ln_res(const float* __restrict__ A, const float* __restrict__ R,
                       const int* __restrict__ rmap,
                       const float* __restrict__ g, const float* __restrict__ beta,
                       float* __restrict__ out,
                       __nv_bfloat16* __restrict__ outH, __nv_bfloat16* __restrict__ outL)
{
    int row = blockIdx.x;
    int tid = threadIdx.x;   // 128
    __shared__ float red [128];
    __shared__ float red2[128];
    int rrow = rmap ? rmap[row] : row;
    float4 x = ((const float4*)(A + (size_t)row*DM))[tid];
    float4 r = ((const float4*)(R + (size_t)rrow*DM))[tid];
    x.x += r.x; x.y += r.y; x.z += r.z; x.w += r.w;
    red [tid] = x.x + x.y + x.z + x.w;
    red2[tid] = x.x*x.x + x.y*x.y + x.z*x.z + x.w*x.w;
    __syncthreads();
    #pragma unroll
    for (int o = 64; o > 0; o >>= 1) {
        if (tid < o) { red[tid] += red[tid+o]; red2[tid] += red2[tid+o]; }
        __syncthreads();
    }
    float mean = red[0] * (1.f/512.f);
    float var  = red2[0] * (1.f/512.f) - mean*mean;
    float inv  = rsqrtf(var + 1e-5f);
    float4 gg = ((const float4*)g)[tid];
    float4 bb = ((const float4*)beta)[tid];
    float4 o4;
    o4.x = (x.x - mean)*inv*gg.x + bb.x;
    o4.y = (x.y - mean)*inv*gg.y + bb.y;
    o4.z = (x.z - mean)*inv*gg.z + bb.z;
    o4.w = (x.w - mean)*inv*gg.w + bb.w;
    ((float4*)(out + (size_t)row*DM))[tid] = o4;
    if (outH) {
        size_t o = (size_t)row * DM + tid * 4;
        float h0 = __bfloat162float(__float2bfloat16(o4.x));
        float h1 = __bfloat162float(__float2bfloat16(o4.y));
        float h2 = __bfloat162float(__float2bfloat16(o4.z));
        float h3 = __bfloat162float(__float2bfloat16(o4.w));
        uint2 uh, ul;
        uh.x = pack_bf2(o4.x, o4.y);
        uh.y = pack_bf2(o4.z, o4.w);
        ul.x = pack_bf2(o4.x - h0, o4.y - h1);
        ul.y = pack_bf2(o4.z - h2, o4.w - h3);
        *(uint2*)(outH + o) = uh;
        *(uint2*)(outL + o) = ul;
    }
}

// ============================================================
// Flash-style attention; writes ctx directly as bf16 hi/lo.
// ============================================================
__global__ __launch_bounds__(128, 8)
void attn_flash(const float* __restrict__ Q, const float* __restrict__ Kb,
                const float* __restrict__ Vb, const int* __restrict__ mask,
                __nv_bfloat16* __restrict__ ctxH, __nv_bfloat16* __restrict__ ctxL,
                int Lq, int Lv)
{
    const int qt = blockIdx.x;
    const int h  = blockIdx.y;
    const int b  = blockIdx.z;
    const int t  = threadIdx.x;
    const int tq = t >> 3;
    const int kc = t & 7;
    const int q  = qt * 16 + tq;
    const bool qvalid = q < Lq;
    const int d0 = kc * 8;

    __shared__ float sQ[16][68];
    __shared__ float sK[32][68];
    __shared__ float sV[32][68];
    __shared__ float sP[16][36];

    #pragma unroll
    for (int i = 0; i < 2; ++i) {
        int idx = t + i * 128;
        int r  = idx >> 4;
        int c4 = idx & 15;
        int qq = qt * 16 + r;
        float4 v = make_float4(0.f, 0.f, 0.f, 0.f);
        if (qq < Lq) {
            v = *(const float4*)(Q + ((size_t)(b * Lq + qq)) * DM + h * DKH + c4 * 4);
        }
        *(float4*)&sQ[r][c4 * 4] = v;
    }

    float acc[8] = {0.f, 0.f, 0.f, 0.f, 0.f, 0.f, 0.f, 0.f};
    float m_run = -INFINITY;
    float l_run = 0.f;
    const int* mrow = mask + ((size_t)(b * Lq + (qvalid ? q : 0))) * Lv;

    for (int kv0 = 0; kv0 < Lv; kv0 += 32) {
        __syncthreads();
        #pragma unroll
        for (int i = 0; i < 4; ++i) {
            int idx = t + i * 128;
            int r  = idx >> 4;
            int c4 = idx & 15;
            int kv = kv0 + r;
            float4 kvv = make_float4(0.f, 0.f, 0.f, 0.f);
            float4 vvv = make_float4(0.f, 0.f, 0.f, 0.f);
            if (kv < Lv) {
                size_t base = ((size_t)(b * Lv + kv)) * DM + h * DKH + c4 * 4;
                kvv = *(const float4*)(Kb + base);
                vvv = *(const float4*)(Vb + base);
            }
            *(float4*)&sK[r][c4 * 4] = kvv;
            *(float4*)&sV[r][c4 * 4] = vvv;
        }
        __syncthreads();

        float s[4];
        #pragma unroll
        for (int c = 0; c < 4; ++c) {
            int k  = kc * 4 + c;
            int kv = kv0 + k;
            bool msk = true;
            if (qvalid && kv < Lv) {
                msk = (mrow[kv] != 0);
            }
            float a = 0.f;
            #pragma unroll
            for (int d4 = 0; d4 < 16; ++d4) {
                float4 qv = *(const float4*)&sQ[tq][d4 * 4];
                float4 kk = *(const float4*)&sK[k][d4 * 4];
                a += qv.x*kk.x + qv.y*kk.y + qv.z*kk.z + qv.w*kk.w;
            }
            s[c] = msk ? -INFINITY : a * 0.125f;
        }
        float tm = fmaxf(fmaxf(s[0], s[1]), fmaxf(s[2], s[3]));
        tm = fmaxf(tm, __shfl_xor_sync(0xffffffffu, tm, 1));
        tm = fmaxf(tm, __shfl_xor_sync(0xffffffffu, tm, 2));
        tm = fmaxf(tm, __shfl_xor_sync(0xffffffffu, tm, 4));
        float newm  = fmaxf(m_run, tm);
        float scale = __expf(fminf(m_run - newm, 0.f));
        float ts = 0.f;
        #pragma unroll
        for (int c = 0; c < 4; ++c) {
            float p = (s[c] == -INFINITY) ? 0.f : __expf(s[c] - newm);
            sP[tq][kc * 4 + c] = p;
            ts += p;
        }
        ts += __shfl_xor_sync(0xffffffffu, ts, 1);
        ts += __shfl_xor_sync(0xffffffffu, ts, 2);
        ts += __shfl_xor_sync(0xffffffffu, ts, 4);
        l_run = l_run * scale + ts;
        m_run = newm;
        #pragma unroll
        for (int j = 0; j < 8; ++j) acc[j] *= scale;
        __syncwarp();

        #pragma unroll 8
        for (int k = 0; k < 32; ++k) {
            float p = sP[tq][k];
            float4 v0 = *(const float4*)&sV[k][d0];
            float4 v1 = *(const float4*)&sV[k][d0 + 4];
            acc[0] += p * v0.x; acc[1] += p * v0.y; acc[2] += p * v0.z; acc[3] += p * v0.w;
            acc[4] += p * v1.x; acc[5] += p * v1.y; acc[6] += p * v1.z; acc[7] += p * v1.w;
        }
    }

    if (qvalid) {
        float inv = 1.f / l_run;
        float o[8];
        #pragma unroll
        for (int j = 0; j < 8; ++j) o[j] = acc[j] * inv;
        size_t off = ((size_t)(b * Lq + q)) * DM + h * DKH + d0;
        uint4 uh, ul;
        uh.x = pack_bf2(o[0], o[1]); uh.y = pack_bf2(o[2], o[3]);
        uh.z = pack_bf2(o[4], o[5]); uh.w = pack_bf2(o[6], o[7]);
        float hh[8];
        #pragma unroll
        for (int j = 0; j < 8; ++j) hh[j] = __bfloat162float(__float2bfloat16(o[j]));
        ul.x = pack_bf2(o[0]-hh[0], o[1]-hh[1]); ul.y = pack_bf2(o[2]-hh[2], o[3]-hh[3]);
        ul.z = pack_bf2(o[4]-hh[4], o[5]-hh[5]); ul.w = pack_bf2(o[6]-hh[6], o[7]-hh[7]);
        *(uint4*)(ctxH + off) = uh;
        *(uint4*)(ctxL + off) = ul;
    }
}

// ============================================================
// launcher
// ============================================================
extern "C" void kernel_launch(void* const* d_in, const int* in_sizes, int n_in,
                              void* d_out, int out_size)
{
    const float* ent   = (const float*)d_in[0];
    const float* pred  = (const float*)d_in[1];
    const float* w_qs  = (const float*)d_in[2];
    const float* b_qs  = (const float*)d_in[3];
    const float* w_ks  = (const float*)d_in[4];
    const float* b_ks  = (const float*)d_in[5];
    const float* w_vs  = (const float*)d_in[6];
    const float* b_vs  = (const float*)d_in[7];
    const float* w_fc  = (const float*)d_in[8];
    const float* b_fc  = (const float*)d_in[9];
    const float* ln1_g = (const float*)d_in[10];
    const float* ln1_b = (const float*)d_in[11];
    const float* w1    = (const float*)d_in[12];
    const float* b1    = (const float*)d_in[13];
    const float* w2    = (const float*)d_in[14];
    const float* b2    = (const float*)d_in[15];
    const float* ln2_g = (const float*)d_in[16];
    const float* ln2_b = (const float*)d_in[17];
    const int*   amask = (const int*)d_in[18];
    const int*   gidx  = (const int*)d_in[20];

    int Lq  = in_sizes[0] / (BSZ * DM);
    int Lv  = in_sizes[1] / (BSZ * DM);
    int nv  = in_sizes[20];
    int MKV = BSZ * Lv;
    int MQ  = BSZ * Lq;

    float *pQ, *pK, *pV, *pT0, *pX;
    cudaGetSymbolAddress((void**)&pQ,  g_Q);
    cudaGetSymbolAddress((void**)&pK,  g_K);
    cudaGetSymbolAddress((void**)&pV,  g_V);
    cudaGetSymbolAddress((void**)&pT0, g_t0);
    cudaGetSymbolAddress((void**)&pX,  g_x);

    __nv_bfloat16 *predH,*predL,*entH,*entL,*ctxH,*ctxL,*xH,*xL,*hH,*hL;
    __nv_bfloat16 *wqH,*wqL,*wkH,*wkL,*wvH,*wvL,*wfH,*wfL,*w1H,*w1L,*w2H,*w2L;
    cudaGetSymbolAddress((void**)&predH, g_predH); cudaGetSymbolAddress((void**)&predL, g_predL);
    cudaGetSymbolAddress((void**)&entH,  g_entH);  cudaGetSymbolAddress((void**)&entL,  g_entL);
    cudaGetSymbolAddress((void**)&ctxH,  g_ctxH);  cudaGetSymbolAddress((void**)&ctxL,  g_ctxL);
    cudaGetSymbolAddress((void**)&xH,    g_xH);    cudaGetSymbolAddress((void**)&xL,    g_xL);
    cudaGetSymbolAddress((void**)&hH,    g_hH);    cudaGetSymbolAddress((void**)&hL,    g_hL);
    cudaGetSymbolAddress((void**)&wqH,   g_wqH);   cudaGetSymbolAddress((void**)&wqL,   g_wqL);
    cudaGetSymbolAddress((void**)&wkH,   g_wkH);   cudaGetSymbolAddress((void**)&wkL,   g_wkL);
    cudaGetSymbolAddress((void**)&wvH,   g_wvH);   cudaGetSymbolAddress((void**)&wvL,   g_wvL);
    cudaGetSymbolAddress((void**)&wfH,   g_wfH);   cudaGetSymbolAddress((void**)&wfL,   g_wfL);
    cudaGetSymbolAddress((void**)&w1H,   g_w1H);   cudaGetSymbolAddress((void**)&w1L,   g_w1L);
    cudaGetSymbolAddress((void**)&w2H,   g_w2H);   cudaGetSymbolAddress((void**)&w2L,   g_w2L);

    cudaFuncSetAttribute(gemm_t5, cudaFuncAttributeMaxDynamicSharedMemorySize, GEMM_SMEM);

    int n4;
    // launches 0-4 (so launch #5, the K GEMM, is what ncu -s 5 profiles)
    n4 = MKV * DM / 4;  cvt_hl<<<(n4 + 255) / 256, 256>>>(pred, predH, predL, n4);
    n4 = DM * DM / 4;   cvt_hl<<<(n4 + 255) / 256, 256>>>(w_ks, wkH, wkL, n4);
    n4 = DM * DM / 4;   cvt_hl<<<(n4 + 255) / 256, 256>>>(w_vs, wvH, wvL, n4);
    n4 = MQ * DM / 4;   cvt_hl<<<(n4 + 255) / 256, 256>>>(ent, entH, entL, n4);
    n4 = DM * DM / 4;   cvt_hl<<<(n4 + 255) / 256, 256>>>(w_qs, wqH, wqL, n4);

    // K, V, Q projections
    {
        dim3 grd(DM / TBN, (MKV + TBM - 1) / TBM);
        gemm_t5<<<grd, 256, GEMM_SMEM>>>(predH, predL, nullptr, wkH, wkL, b_ks,
                                         pK, nullptr, nullptr, MKV, DM, DM, 0);
        gemm_t5<<<grd, 256, GEMM_SMEM>>>(predH, predL, nullptr, wvH, wvL, b_vs,
                                         pV, nullptr, nullptr, MKV, DM, DM, 0);
    }
    {
        dim3 grd(DM / TBN, (MQ + TBM - 1) / TBM);
        gemm_t5<<<grd, 256, GEMM_SMEM>>>(entH, entL, nullptr, wqH, wqL, b_qs,
                                         pQ, nullptr, nullptr, MQ, DM, DM, 0);
    }
    // attention -> ctx (bf16 HL, padded)
    {
        dim3 grd((Lq + 15) / 16, NH, BSZ);
        attn_flash<<<grd, 128>>>(pQ, pK, pV, amask, ctxH, ctxL, Lq, Lv);
    }
    // fc projection (gathers valid rows) + LN1
    n4 = DM * DM / 4;   cvt_hl<<<(n4 + 255) / 256, 256>>>(w_fc, wfH, wfL, n4);
    {
        dim3 grd(DM / TBN, (nv + TBM - 1) / TBM);
        gemm_t5<<<grd, 256, GEMM_SMEM>>>(ctxH, ctxL, gidx, wfH, wfL, b_fc,
                                         pT0, nullptr, nullptr, nv, DM, DM, 0);
        ln_res<<<nv, 128>>>(pT0, ent, gidx, ln1_g, ln1_b, pX, xH, xL);
    }
    // FFN
    n4 = DI * DM / 4;   cvt_hl<<<(n4 + 255) / 256, 256>>>(w1, w1H, w1L, n4);
    {
        dim3 grd(DI / TBN, (nv + TBM - 1) / TBM);
        gemm_t5<<<grd, 256, GEMM_SMEM>>>(xH, xL, nullptr, w1H, w1L, b1,
                                         nullptr, hH, hL, nv, DI, DM, 1);
    }
    n4 = DM * DI / 4;   cvt_hl<<<(n4 + 255) / 256, 256>>>(w2, w2H, w2L, n4);
    {
        dim3 grd(DM / TBN, (nv + TBM - 1) / TBM);
        gemm_t5<<<grd, 256, GEMM_SMEM>>>(hH, hL, nullptr, w2H, w2L, b2,
                                         pT0, nullptr, nullptr, nv, DM, DI, 0);
        ln_res<<<nv, 128>>>(pT0, pX, nullptr, ln2_g, ln2_b, (float*)d_out, nullptr, nullptr);
    }
}

// round 8
// speedup vs baseline: 1.0764x; 1.0764x over previous
#include <cuda_runtime.h>
#include <cuda_bf16.h>
#include <cstdint>
#include <math.h>

#define DM 512
#define DI 2048
#define NH 8
#define DKH 64
#define BSZ 32
#define MAXROWS (32*160)
#define MAXKV   (32*640)

// ---- fp32 scratch ----
__device__ float g_Q  [MAXROWS*DM];
__device__ float g_K  [MAXKV*DM];
__device__ float g_V  [MAXKV*DM];
__device__ float g_t0 [MAXROWS*DM];
__device__ float g_x  [MAXROWS*DM];

// ---- bf16 hi/lo scratch ----
__device__ __nv_bfloat16 g_predH[MAXKV*DM],   g_predL[MAXKV*DM];
__device__ __nv_bfloat16 g_entH [MAXROWS*DM], g_entL [MAXROWS*DM];
__device__ __nv_bfloat16 g_ctxH [MAXROWS*DM], g_ctxL [MAXROWS*DM];
__device__ __nv_bfloat16 g_xH   [MAXROWS*DM], g_xL   [MAXROWS*DM];
__device__ __nv_bfloat16 g_hH   [MAXROWS*DI], g_hL   [MAXROWS*DI];
__device__ __nv_bfloat16 g_wqH[DM*DM], g_wqL[DM*DM];
__device__ __nv_bfloat16 g_wkH[DM*DM], g_wkL[DM*DM];
__device__ __nv_bfloat16 g_wvH[DM*DM], g_wvL[DM*DM];
__device__ __nv_bfloat16 g_wfH[DM*DM], g_wfL[DM*DM];
__device__ __nv_bfloat16 g_w1H[DI*DM], g_w1L[DI*DM];
__device__ __nv_bfloat16 g_w2H[DM*DI], g_w2L[DM*DI];

__device__ __forceinline__ unsigned pack_bf2(float a, float b) {
    __nv_bfloat162 t = __floats2bfloat162_rn(a, b);
    return *(unsigned*)&t;
}

// ============================================================
// fp32 -> bf16 hi/lo conversion
// ============================================================
__global__ void cvt_hl(const float* __restrict__ in,
                       __nv_bfloat16* __restrict__ hi,
                       __nv_bfloat16* __restrict__ lo, int n4)
{
    int i = blockIdx.x * blockDim.x + threadIdx.x;
    if (i >= n4) return;
    float4 v = ((const float4*)in)[i];
    float h0 = __bfloat162float(__float2bfloat16(v.x));
    float h1 = __bfloat162float(__float2bfloat16(v.y));
    float h2 = __bfloat162float(__float2bfloat16(v.z));
    float h3 = __bfloat162float(__float2bfloat16(v.w));
    uint2 uh, ul;
    uh.x = pack_bf2(v.x, v.y);
    uh.y = pack_bf2(v.z, v.w);
    ul.x = pack_bf2(v.x - h0, v.y - h1);
    ul.y = pack_bf2(v.z - h2, v.w - h3);
    *(uint2*)(hi + 4 * (size_t)i) = uh;
    *(uint2*)(lo + 4 * (size_t)i) = ul;
}

// ============================================================
// Pipelined mma.sync GEMM: C[M,N] = A[M,K] @ W[N,K]^T + bias.
// A,W bf16 hi/lo; 3 passes (AhWh + AhWl + AlWh), fp32 accum.
// 128x128 tile, BK=32, 256 thr, warp tile 64x32.
// 2-stage cp.async pipeline; smem rows padded to 40 elems (80B).
// ============================================================
#define PBM 128
#define PBN 128
#define PBK 32
#define PLD 40
#define TILE_B (PBM*PLD*2)        // 10240 B per tile
#define STAGE_B (4*TILE_B)        // 40960 B per stage
#define GEMM_SMEM (2*STAGE_B)     // 81920 B dynamic

__device__ __forceinline__ unsigned smem_u32(const void* p) {
    return (unsigned)__cvta_generic_to_shared(p);
}
__device__ __forceinline__ void cp16(unsigned dst, const void* src, int sz) {
    asm volatile("cp.async.cg.shared.global [%0], [%1], 16, %2;"
        :: "r"(dst), "l"(src), "r"(sz) : "memory");
}
__device__ __forceinline__ void ldsm_x4(unsigned* r, const void* p) {
    unsigned a = smem_u32(p);
    asm volatile("ldmatrix.sync.aligned.m8n8.x4.shared.b16 {%0,%1,%2,%3}, [%4];"
        : "=r"(r[0]), "=r"(r[1]), "=r"(r[2]), "=r"(r[3]) : "r"(a));
}
__device__ __forceinline__ void ldsm_x2(unsigned* r, const void* p) {
    unsigned a = smem_u32(p);
    asm volatile("ldmatrix.sync.aligned.m8n8.x2.shared.b16 {%0,%1}, [%2];"
        : "=r"(r[0]), "=r"(r[1]) : "r"(a));
}
__device__ __forceinline__ void mma16816(float* c, const unsigned* a, const unsigned* b) {
    asm volatile("mma.sync.aligned.m16n8k16.row.col.f32.bf16.bf16.f32 "
        "{%0,%1,%2,%3}, {%4,%5,%6,%7}, {%8,%9}, {%0,%1,%2,%3};"
        : "+f"(c[0]), "+f"(c[1]), "+f"(c[2]), "+f"(c[3])
        : "r"(a[0]), "r"(a[1]), "r"(a[2]), "r"(a[3]), "r"(b[0]), "r"(b[1]));
}

__global__ __launch_bounds__(256, 2)
void gemm_pipe(const __nv_bfloat16* __restrict__ Ah, const __nv_bfloat16* __restrict__ Al,
               const int* __restrict__ rmap,
               const __nv_bfloat16* __restrict__ Wh, const __nv_bfloat16* __restrict__ Wl,
               const float* __restrict__ bias,
               float* __restrict__ Cf,
               __nv_bfloat16* __restrict__ Ch, __nv_bfloat16* __restrict__ Cl,
               int M, int N, int K, int relu)
{
    extern __shared__ char sm[];
    __shared__ int irows[PBM];

    const int tid  = threadIdx.x;
    const int lane = tid & 31;
    const int wid  = tid >> 5;
    const int wm   = wid >> 2;
    const int wn   = wid & 3;
    const int bm = blockIdx.y * PBM;
    const int bn = blockIdx.x * PBN;

    if (tid < PBM) {
        int ar = bm + tid;
        irows[tid] = (ar < M) ? (rmap ? rmap[ar] : ar) : -1;
    }
    __syncthreads();

    // ---- per-thread copy slots: 8 x 16B chunks per stage ----
    // idx = tid + i*256 (0..2047): buf = idx>>9, j = idx&511, r = j>>2, c16 = j&3
    const __nv_bfloat16* srcs[4] = {Ah, Al, Wh, Wl};

    float acc[4][4][4];
    #pragma unroll
    for (int mi = 0; mi < 4; ++mi) {
        #pragma unroll
        for (int ni = 0; ni < 4; ++ni) {
            #pragma unroll
            for (int j = 0; j < 4; ++j) acc[mi][ni][j] = 0.f;
        }
    }

    const unsigned smb = smem_u32(sm);
    const int nIter = K / PBK;

    // issue one stage's loads (8 chunks/thread) + commit
    auto issue_stage = [&](int stage, int k0) {
        #pragma unroll
        for (int i = 0; i < 8; ++i) {
            int idx = tid + i * 256;
            int buf = idx >> 9;
            int j   = idx & 511;
            int r   = j >> 2;
            int c16 = j & 3;
            int grow;
            if (buf < 2) {
                grow = irows[r];
            } else {
                int wr = bn + r;
                grow = (wr < N) ? wr : -1;
            }
            unsigned dst = smb + stage * STAGE_B + buf * TILE_B + r * 80 + c16 * 16;
            const char* src = (const char*)srcs[buf]
                            + ((size_t)(grow < 0 ? 0 : grow) * K + k0) * 2 + c16 * 16;
            cp16(dst, src, grow >= 0 ? 16 : 0);
        }
        asm volatile("cp.async.commit_group;" ::: "memory");
    };

    issue_stage(0, 0);

    for (int c = 0; c < nIter; ++c) {
        if (c + 1 < nIter) {
            issue_stage((c + 1) & 1, (c + 1) * PBK);
            asm volatile("cp.async.wait_group 1;" ::: "memory");
        } else {
            asm volatile("cp.async.wait_group 0;" ::: "memory");
        }
        __syncthreads();

        char* st = sm + (c & 1) * STAGE_B;
        __nv_bfloat16 (*sAh)[PLD] = (__nv_bfloat16 (*)[PLD])(st);
        __nv_bfloat16 (*sAl)[PLD] = (__nv_bfloat16 (*)[PLD])(st + TILE_B);
        __nv_bfloat16 (*sWh)[PLD] = (__nv_bfloat16 (*)[PLD])(st + 2 * TILE_B);
        __nv_bfloat16 (*sWl)[PLD] = (__nv_bfloat16 (*)[PLD])(st + 3 * TILE_B);

        #pragma unroll
        for (int ks = 0; ks < 2; ++ks) {
            const int kk = ks * 16;
            unsigned ah[4][4], al[4][4], bh[4][2], bl[4][2];
            const int lr = lane & 15;
            const int lk = (lane >> 4) * 8;
            #pragma unroll
            for (int mi = 0; mi < 4; ++mi) {
                ldsm_x4(ah[mi], &sAh[wm * 64 + mi * 16 + lr][kk + lk]);
                ldsm_x4(al[mi], &sAl[wm * 64 + mi * 16 + lr][kk + lk]);
            }
            const int l8  = lane & 7;
            const int lk2 = ((lane >> 3) & 1) * 8;
            #pragma unroll
            for (int ni = 0; ni < 4; ++ni) {
                ldsm_x2(bh[ni], &sWh[wn * 32 + ni * 8 + l8][kk + lk2]);
                ldsm_x2(bl[ni], &sWl[wn * 32 + ni * 8 + l8][kk + lk2]);
            }
            #pragma unroll
            for (int mi = 0; mi < 4; ++mi) {
                #pragma unroll
                for (int ni = 0; ni < 4; ++ni) {
                    mma16816(acc[mi][ni], ah[mi], bh[ni]);
                    mma16816(acc[mi][ni], ah[mi], bl[ni]);
                    mma16816(acc[mi][ni], al[mi], bh[ni]);
                }
            }
        }
        __syncthreads();
    }

    // ---- epilogue ----
    #pragma unroll
    for (int mi = 0; mi < 4; ++mi) {
        int r0 = bm + wm * 64 + mi * 16 + (lane >> 2);
        #pragma unroll
        for (int ni = 0; ni < 4; ++ni) {
            int c = bn + wn * 32 + ni * 8 + (lane & 3) * 2;
            float b0 = bias[c];
            float b1 = bias[c + 1];
            float v0 = acc[mi][ni][0] + b0;
            float v1 = acc[mi][ni][1] + b1;
            float v2 = acc[mi][ni][2] + b0;
            float v3 = acc[mi][ni][3] + b1;
            if (relu) {
                v0 = fmaxf(v0, 0.f); v1 = fmaxf(v1, 0.f);
                v2 = fmaxf(v2, 0.f); v3 = fmaxf(v3, 0.f);
            }
            if (r0 < M) {
                size_t o = (size_t)r0 * N + c;
                if (Cf) *(float2*)(Cf + o) = make_float2(v0, v1);
                if (Ch) {
                    float h0 = __bfloat162float(__float2bfloat16(v0));
                    float h1 = __bfloat162float(__float2bfloat16(v1));
                    *(unsigned*)(Ch + o) = pack_bf2(v0, v1);
                    *(unsigned*)(Cl + o) = pack_bf2(v0 - h0, v1 - h1);
                }
            }
            if (r0 + 8 < M) {
                size_t o = (size_t)(r0 + 8) * N + c;
                if (Cf) *(float2*)(Cf + o) = make_float2(v2, v3);
                if (Ch) {
                    float h2 = __bfloat162float(__float2bfloat16(v2));
                    float h3 = __bfloat162float(__float2bfloat16(v3));
                    *(unsigned*)(Ch + o) = pack_bf2(v2, v3);
                    *(unsigned*)(Cl + o) = pack_bf2(v2 - h2, v3 - h3);
                }
            }
        }
    }
}

// ============================================================
// LayerNorm with residual; optional bf16 hi/lo secondary output.
// ============================================================
__global__ void ln_res(const float* __restrict__ A, const float* __restrict__ R,
                       const int* __restrict__ rmap,
                       const float* __restrict__ g, const float* __restrict__ beta,
                       float* __restrict__ out,
                       __nv_bfloat16* __restrict__ outH, __nv_bfloat16* __restrict__ outL)
{
    int row = blockIdx.x;
    int tid = threadIdx.x;   // 128
    __shared__ float red [128];
    __shared__ float red2[128];
    int rrow = rmap ? rmap[row] : row;
    float4 x = ((const float4*)(A + (size_t)row*DM))[tid];
    float4 r = ((const float4*)(R + (size_t)rrow*DM))[tid];
    x.x += r.x; x.y += r.y; x.z += r.z; x.w += r.w;
    red [tid] = x.x + x.y + x.z + x.w;
    red2[tid] = x.x*x.x + x.y*x.y + x.z*x.z + x.w*x.w;
    __syncthreads();
    #pragma unroll
    for (int o = 64; o > 0; o >>= 1) {
        if (tid < o) { red[tid] += red[tid+o]; red2[tid] += red2[tid+o]; }
        __syncthreads();
    }
    float mean = red[0] * (1.f/512.f);
    float var  = red2[0] * (1.f/512.f) - mean*mean;
    float inv  = rsqrtf(var + 1e-5f);
    float4 gg = ((const float4*)g)[tid];
    float4 bb = ((const float4*)beta)[tid];
    float4 o4;
    o4.x = (x.x - mean)*inv*gg.x + bb.x;
    o4.y = (x.y - mean)*inv*gg.y + bb.y;
    o4.z = (x.z - mean)*inv*gg.z + bb.z;
    o4.w = (x.w - mean)*inv*gg.w + bb.w;
    ((float4*)(out + (size_t)row*DM))[tid] = o4;
    if (outH) {
        size_t o = (size_t)row * DM + tid * 4;
        float h0 = __bfloat162float(__float2bfloat16(o4.x));
        float h1 = __bfloat162float(__float2bfloat16(o4.y));
        float h2 = __bfloat162float(__float2bfloat16(o4.z));
        float h3 = __bfloat162float(__float2bfloat16(o4.w));
        uint2 uh, ul;
        uh.x = pack_bf2(o4.x, o4.y);
        uh.y = pack_bf2(o4.z, o4.w);
        ul.x = pack_bf2(o4.x - h0, o4.y - h1);
        ul.y = pack_bf2(o4.z - h2, o4.w - h3);
        *(uint2*)(outH + o) = uh;
        *(uint2*)(outL + o) = ul;
    }
}

// ============================================================
// Flash-style attention; writes ctx directly as bf16 hi/lo.
// ============================================================
__global__ __launch_bounds__(128, 8)
void attn_flash(const float* __restrict__ Q, const float* __restrict__ Kb,
                const float* __restrict__ Vb, const int* __restrict__ mask,
                __nv_bfloat16* __restrict__ ctxH, __nv_bfloat16* __restrict__ ctxL,
                int Lq, int Lv)
{
    const int qt = blockIdx.x;
    const int h  = blockIdx.y;
    const int b  = blockIdx.z;
    const int t  = threadIdx.x;
    const int tq = t >> 3;
    const int kc = t & 7;
    const int q  = qt * 16 + tq;
    const bool qvalid = q < Lq;
    const int d0 = kc * 8;

    __shared__ float sQ[16][68];
    __shared__ float sK[32][68];
    __shared__ float sV[32][68];
    __shared__ float sP[16][36];

    #pragma unroll
    for (int i = 0; i < 2; ++i) {
        int idx = t + i * 128;
        int r  = idx >> 4;
        int c4 = idx & 15;
        int qq = qt * 16 + r;
        float4 v = make_float4(0.f, 0.f, 0.f, 0.f);
        if (qq < Lq) {
            v = *(const float4*)(Q + ((size_t)(b * Lq + qq)) * DM + h * DKH + c4 * 4);
        }
        *(float4*)&sQ[r][c4 * 4] = v;
    }

    float acc[8] = {0.f, 0.f, 0.f, 0.f, 0.f, 0.f, 0.f, 0.f};
    float m_run = -INFINITY;
    float l_run = 0.f;
    const int* mrow = mask + ((size_t)(b * Lq + (qvalid ? q : 0))) * Lv;

    for (int kv0 = 0; kv0 < Lv; kv0 += 32) {
        __syncthreads();
        #pragma unroll
        for (int i = 0; i < 4; ++i) {
            int idx = t + i * 128;
            int r  = idx >> 4;
            int c4 = idx & 15;
            int kv = kv0 + r;
            float4 kvv = make_float4(0.f, 0.f, 0.f, 0.f);
            float4 vvv = make_float4(0.f, 0.f, 0.f, 0.f);
            if (kv < Lv) {
                size_t base = ((size_t)(b * Lv + kv)) * DM + h * DKH + c4 * 4;
                kvv = *(const float4*)(Kb + base);
                vvv = *(const float4*)(Vb + base);
            }
            *(float4*)&sK[r][c4 * 4] = kvv;
            *(float4*)&sV[r][c4 * 4] = vvv;
        }
        __syncthreads();

        float s[4];
        #pragma unroll
        for (int c = 0; c < 4; ++c) {
            int k  = kc * 4 + c;
            int kv = kv0 + k;
            bool msk = true;
            if (qvalid && kv < Lv) {
                msk = (mrow[kv] != 0);
            }
            float a = 0.f;
            #pragma unroll
            for (int d4 = 0; d4 < 16; ++d4) {
                float4 qv = *(const float4*)&sQ[tq][d4 * 4];
                float4 kk = *(const float4*)&sK[k][d4 * 4];
                a += qv.x*kk.x + qv.y*kk.y + qv.z*kk.z + qv.w*kk.w;
            }
            s[c] = msk ? -INFINITY : a * 0.125f;
        }
        float tm = fmaxf(fmaxf(s[0], s[1]), fmaxf(s[2], s[3]));
        tm = fmaxf(tm, __shfl_xor_sync(0xffffffffu, tm, 1));
        tm = fmaxf(tm, __shfl_xor_sync(0xffffffffu, tm, 2));
        tm = fmaxf(tm, __shfl_xor_sync(0xffffffffu, tm, 4));
        float newm  = fmaxf(m_run, tm);
        float scale = __expf(fminf(m_run - newm, 0.f));
        float ts = 0.f;
        #pragma unroll
        for (int c = 0; c < 4; ++c) {
            float p = (s[c] == -INFINITY) ? 0.f : __expf(s[c] - newm);
            sP[tq][kc * 4 + c] = p;
            ts += p;
        }
        ts += __shfl_xor_sync(0xffffffffu, ts, 1);
        ts += __shfl_xor_sync(0xffffffffu, ts, 2);
        ts += __shfl_xor_sync(0xffffffffu, ts, 4);
        l_run = l_run * scale + ts;
        m_run = newm;
        #pragma unroll
        for (int j = 0; j < 8; ++j) acc[j] *= scale;
        __syncwarp();

        #pragma unroll 8
        for (int k = 0; k < 32; ++k) {
            float p = sP[tq][k];
            float4 v0 = *(const float4*)&sV[k][d0];
            float4 v1 = *(const float4*)&sV[k][d0 + 4];
            acc[0] += p * v0.x; acc[1] += p * v0.y; acc[2] += p * v0.z; acc[3] += p * v0.w;
            acc[4] += p * v1.x; acc[5] += p * v1.y; acc[6] += p * v1.z; acc[7] += p * v1.w;
        }
    }

    if (qvalid) {
        float inv = 1.f / l_run;
        float o[8];
        #pragma unroll
        for (int j = 0; j < 8; ++j) o[j] = acc[j] * inv;
        size_t off = ((size_t)(b * Lq + q)) * DM + h * DKH + d0;
        uint4 uh, ul;
        uh.x = pack_bf2(o[0], o[1]); uh.y = pack_bf2(o[2], o[3]);
        uh.z = pack_bf2(o[4], o[5]); uh.w = pack_bf2(o[6], o[7]);
        float hh[8];
        #pragma unroll
        for (int j = 0; j < 8; ++j) hh[j] = __bfloat162float(__float2bfloat16(o[j]));
        ul.x = pack_bf2(o[0]-hh[0], o[1]-hh[1]); ul.y = pack_bf2(o[2]-hh[2], o[3]-hh[3]);
        ul.z = pack_bf2(o[4]-hh[4], o[5]-hh[5]); ul.w = pack_bf2(o[6]-hh[6], o[7]-hh[7]);
        *(uint4*)(ctxH + off) = uh;
        *(uint4*)(ctxL + off) = ul;
    }
}

// ============================================================
// launcher
// ============================================================
extern "C" void kernel_launch(void* const* d_in, const int* in_sizes, int n_in,
                              void* d_out, int out_size)
{
    const float* ent   = (const float*)d_in[0];
    const float* pred  = (const float*)d_in[1];
    const float* w_qs  = (const float*)d_in[2];
    const float* b_qs  = (const float*)d_in[3];
    const float* w_ks  = (const float*)d_in[4];
    const float* b_ks  = (const float*)d_in[5];
    const float* w_vs  = (const float*)d_in[6];
    const float* b_vs  = (const float*)d_in[7];
    const float* w_fc  = (const float*)d_in[8];
    const float* b_fc  = (const float*)d_in[9];
    const float* ln1_g = (const float*)d_in[10];
    const float* ln1_b = (const float*)d_in[11];
    const float* w1    = (const float*)d_in[12];
    const float* b1    = (const float*)d_in[13];
    const float* w2    = (const float*)d_in[14];
    const float* b2    = (const float*)d_in[15];
    const float* ln2_g = (const float*)d_in[16];
    const float* ln2_b = (const float*)d_in[17];
    const int*   amask = (const int*)d_in[18];
    const int*   gidx  = (const int*)d_in[20];

    int Lq  = in_sizes[0] / (BSZ * DM);
    int Lv  = in_sizes[1] / (BSZ * DM);
    int nv  = in_sizes[20];
    int MKV = BSZ * Lv;
    int MQ  = BSZ * Lq;

    float *pQ, *pK, *pV, *pT0, *pX;
    cudaGetSymbolAddress((void**)&pQ,  g_Q);
    cudaGetSymbolAddress((void**)&pK,  g_K);
    cudaGetSymbolAddress((void**)&pV,  g_V);
    cudaGetSymbolAddress((void**)&pT0, g_t0);
    cudaGetSymbolAddress((void**)&pX,  g_x);

    __nv_bfloat16 *predH,*predL,*entH,*entL,*ctxH,*ctxL,*xH,*xL,*hH,*hL;
    __nv_bfloat16 *wqH,*wqL,*wkH,*wkL,*wvH,*wvL,*wfH,*wfL,*w1H,*w1L,*w2H,*w2L;
    cudaGetSymbolAddress((void**)&predH, g_predH); cudaGetSymbolAddress((void**)&predL, g_predL);
    cudaGetSymbolAddress((void**)&entH,  g_entH);  cudaGetSymbolAddress((void**)&entL,  g_entL);
    cudaGetSymbolAddress((void**)&ctxH,  g_ctxH);  cudaGetSymbolAddress((void**)&ctxL,  g_ctxL);
    cudaGetSymbolAddress((void**)&xH,    g_xH);    cudaGetSymbolAddress((void**)&xL,    g_xL);
    cudaGetSymbolAddress((void**)&hH,    g_hH);    cudaGetSymbolAddress((void**)&hL,    g_hL);
    cudaGetSymbolAddress((void**)&wqH,   g_wqH);   cudaGetSymbolAddress((void**)&wqL,   g_wqL);
    cudaGetSymbolAddress((void**)&wkH,   g_wkH);   cudaGetSymbolAddress((void**)&wkL,   g_wkL);
    cudaGetSymbolAddress((void**)&wvH,   g_wvH);   cudaGetSymbolAddress((void**)&wvL,   g_wvL);
    cudaGetSymbolAddress((void**)&wfH,   g_wfH);   cudaGetSymbolAddress((void**)&wfL,   g_wfL);
    cudaGetSymbolAddress((void**)&w1H,   g_w1H);   cudaGetSymbolAddress((void**)&w1L,   g_w1L);
    cudaGetSymbolAddress((void**)&w2H,   g_w2H);   cudaGetSymbolAddress((void**)&w2L,   g_w2L);

    cudaFuncSetAttribute(gemm_pipe, cudaFuncAttributeMaxDynamicSharedMemorySize, GEMM_SMEM);

    int n4;
    // launches 0-4 (launch #5 = K GEMM for ncu -s 5)
    n4 = MKV * DM / 4;  cvt_hl<<<(n4 + 255) / 256, 256>>>(pred, predH, predL, n4);
    n4 = DM * DM / 4;   cvt_hl<<<(n4 + 255) / 256, 256>>>(w_ks, wkH, wkL, n4);
    n4 = DM * DM / 4;   cvt_hl<<<(n4 + 255) / 256, 256>>>(w_vs, wvH, wvL, n4);
    n4 = MQ * DM / 4;   cvt_hl<<<(n4 + 255) / 256, 256>>>(ent, entH, entL, n4);
    n4 = DM * DM / 4;   cvt_hl<<<(n4 + 255) / 256, 256>>>(w_qs, wqH, wqL, n4);

    // K, V, Q projections
    {
        dim3 grd(DM / PBN, (MKV + PBM - 1) / PBM);
        gemm_pipe<<<grd, 256, GEMM_SMEM>>>(predH, predL, nullptr, wkH, wkL, b_ks,
                                           pK, nullptr, nullptr, MKV, DM, DM, 0);
        gemm_pipe<<<grd, 256, GEMM_SMEM>>>(predH, predL, nullptr, wvH, wvL, b_vs,
                                           pV, nullptr, nullptr, MKV, DM, DM, 0);
    }
    {
        dim3 grd(DM / PBN, (MQ + PBM - 1) / PBM);
        gemm_pipe<<<grd, 256, GEMM_SMEM>>>(entH, entL, nullptr, wqH, wqL, b_qs,
                                           pQ, nullptr, nullptr, MQ, DM, DM, 0);
    }
    // attention -> ctx (bf16 HL, padded)
    {
        dim3 grd((Lq + 15) / 16, NH, BSZ);
        attn_flash<<<grd, 128>>>(pQ, pK, pV, amask, ctxH, ctxL, Lq, Lv);
    }
    // fc projection (gathers valid rows) + LN1
    n4 = DM * DM / 4;   cvt_hl<<<(n4 + 255) / 256, 256>>>(w_fc, wfH, wfL, n4);
    {
        dim3 grd(DM / PBN, (nv + PBM - 1) / PBM);
        gemm_pipe<<<grd, 256, GEMM_SMEM>>>(ctxH, ctxL, gidx, wfH, wfL, b_fc,
                                           pT0, nullptr, nullptr, nv, DM, DM, 0);
        ln_res<<<nv, 128>>>(pT0, ent, gidx, ln1_g, ln1_b, pX, xH, xL);
    }
    // FFN
    n4 = DI * DM / 4;   cvt_hl<<<(n4 + 255) / 256, 256>>>(w1, w1H, w1L, n4);
    {
        dim3 grd(DI / PBN, (nv + PBM - 1) / PBM);
        gemm_pipe<<<grd, 256, GEMM_SMEM>>>(xH, xL, nullptr, w1H, w1L, b1,
                                           nullptr, hH, hL, nv, DI, DM, 1);
    }
    n4 = DM * DI / 4;   cvt_hl<<<(n4 + 255) / 256, 256>>>(w2, w2H, w2L, n4);
    {
        dim3 grd(DM / PBN, (nv + PBM - 1) / PBM);
        gemm_pipe<<<grd, 256, GEMM_SMEM>>>(hH, hL, nullptr, w2H, w2L, b2,
                                           pT0, nullptr, nullptr, nv, DM, DI, 0);
        ln_res<<<nv, 128>>>(pT0, pX, nullptr, ln2_g, ln2_b, (float*)d_out, nullptr, nullptr);
    }
}